// round 11
// baseline (speedup 1.0000x reference)
#include <cuda_runtime.h>

// Math collapse (verified R8-R10): softmax over a size-1 axis == 1.0 exactly, so
//   out[b,c,f] = sum_t x[b,t,f]     (context/W/b are dead inputs).
//
// R10 evidence: K1 (pure streaming read, 32MB) ran ~4us => ~8TB/s, DRAM spec.
// The 3TB/s wall of fused kernels = mixed R/W streams. K2 was the regression:
// 1024 CTAs x (16 redundant L2 loads + only 4 stores) => latency-bound 8.9us.
// This round: K1 unchanged; K2 rebuilt as 256 CTAs x 64KB store blocks with
// 16 independent STG.128/thread, 4x fewer redundant partial reads, and
// evict-first (__stcs) output stores so `out` doesn't evict `x` from L2
// across graph replays.

#define B_ 32
#define T_ 512
#define C_ 256
#define F_ 512

static constexpr int F4       = F_ / 4;        // 128 float4 per row
static constexpr int TPB      = 256;
static constexpr int T_CHUNK  = 16;            // rows per K1 CTA
static constexpr int NCHUNK   = T_ / T_CHUNK;  // 32 partial chunks per b
static constexpr int C_CHUNK  = 32;            // rows per K2 CTA
static constexpr int NCCHUNK  = C_ / C_CHUNK;  // 8 K2 CTAs per b

// Partial sums: [B][NCHUNK][F4] float4 (2MB scratch)
__device__ float4 g_part[B_ * NCHUNK * F4];

__device__ __forceinline__ void f4add(float4& a, const float4& b) {
    a.x += b.x; a.y += b.y; a.z += b.z; a.w += b.w;
}

// ---------------- K1: streaming T-reduction (unchanged from R10) ----------
// CTA (b, chunk) reads a contiguous 32KB block; every warp-LDG.128 is 512B
// of consecutive addresses. Measured ~8TB/s in R10.
__global__ __launch_bounds__(TPB)
void k1_reduce(const float* __restrict__ x) {
    const int b     = blockIdx.x >> 5;        // /NCHUNK
    const int chunk = blockIdx.x & 31;
    const int f4l   = threadIdx.x & (F4 - 1);
    const int rh    = threadIdx.x >> 7;        // 0 or 1

    const float4* xb = reinterpret_cast<const float4*>(x)
                     + ((size_t)b * T_ + chunk * T_CHUNK + rh) * F4 + f4l;

    float4 v0 = __ldg(&xb[ 0 * F4]);
    float4 v1 = __ldg(&xb[ 2 * F4]);
    float4 v2 = __ldg(&xb[ 4 * F4]);
    float4 v3 = __ldg(&xb[ 6 * F4]);
    float4 v4 = __ldg(&xb[ 8 * F4]);
    float4 v5 = __ldg(&xb[10 * F4]);
    float4 v6 = __ldg(&xb[12 * F4]);
    float4 v7 = __ldg(&xb[14 * F4]);
    f4add(v0, v4); f4add(v1, v5); f4add(v2, v6); f4add(v3, v7);
    f4add(v0, v2); f4add(v1, v3);
    f4add(v0, v1);

    __shared__ float4 sm[TPB];
    sm[threadIdx.x] = v0;
    __syncthreads();
    if (threadIdx.x < F4) {
        float4 tot = sm[threadIdx.x];
        f4add(tot, sm[threadIdx.x + F4]);
        g_part[((size_t)b * NCHUNK + chunk) * F4 + threadIdx.x] = tot;
    }
}

// ---------------- K2: sum partials + big-block streaming broadcast --------
// CTA (b, cc) owns out[b, cc*32 .. cc*32+32, :] — a contiguous 64KB block.
// Load phase: 16 independent L2-hit loads/thread (each half-block sums 16
// partial chunks). Store phase: 16 independent STG.128/thread, evict-first.
__global__ __launch_bounds__(TPB)
void k2_broadcast(float* __restrict__ out) {
    const int b   = blockIdx.x >> 3;          // /NCCHUNK
    const int cc  = blockIdx.x & 7;
    const int f4l = threadIdx.x & (F4 - 1);
    const int h   = threadIdx.x >> 7;         // 0/1: each half sums 16 chunks

    const float4* pb = &g_part[((size_t)b * NCHUNK + h * (NCHUNK / 2)) * F4 + f4l];
    float4 s = make_float4(0.f, 0.f, 0.f, 0.f);
#pragma unroll
    for (int k = 0; k < NCHUNK / 2; ++k)
        f4add(s, pb[(size_t)k * F4]);

    __shared__ float4 sm[TPB];
    sm[threadIdx.x] = s;
    __syncthreads();
    if (threadIdx.x < F4) {
        float4 tot = sm[threadIdx.x];
        f4add(tot, sm[threadIdx.x + F4]);
        sm[threadIdx.x] = tot;                // final column sum for (b, f4)
    }
    __syncthreads();

    // 32 rows x 128 float4 = 4096 stores; 16 per thread, warp-contiguous
    // 512B, consecutive across the whole 64KB block. Evict-first: `out` is
    // write-once, keep L2 for x.
    float4* ob = reinterpret_cast<float4*>(out)
               + ((size_t)b * C_ + cc * C_CHUNK) * F4;
#pragma unroll
    for (int k = 0; k < (C_CHUNK * F4) / TPB; ++k) {
        const int idx = (k << 8) + threadIdx.x;    // 0..4095, consecutive
        __stcs(&ob[idx], sm[idx & (F4 - 1)]);
    }
}

extern "C" void kernel_launch(void* const* d_in, const int* in_sizes, int n_in,
                              void* d_out, int out_size) {
    (void)in_sizes; (void)n_in; (void)out_size;
    const float* x = (const float*)d_in[0];   // [B,T,F]; context/W/b dead
    float* out = (float*)d_out;               // [B,C,F]
    k1_reduce<<<B_ * NCHUNK, TPB>>>(x);
    k2_broadcast<<<B_ * NCCHUNK, TPB>>>(out);
}

// round 12
// speedup vs baseline: 1.0251x; 1.0251x over previous
#include <cuda_runtime.h>
#include <cstdint>

// Math collapse (verified R8-R11): softmax over a size-1 axis == 1.0 exactly, so
//   out[b,c,f] = sum_t x[b,t,f]     (context/W/b are dead inputs).
//
// Evidence so far:
//   - Pure streaming reads (K1) run at ~8TB/s (R10: 32MB in ~4.1us).
//   - The 16MB output write costs ~8.8us (~1.9TB/s) via per-thread STG under
//     FOUR different geometries (R8-R11) -> shape-invariant store-path cap.
// This round: change the store PATH. K2 writes the output via
// cp.async.bulk.global.shared::cta (TMA/bulk async proxy, smem -> L2/DRAM),
// bypassing the per-thread LSU store pipeline. B300 measures the TMA chip
// path at the full ~6300 B/cyc LTS cap.

#define B_ 32
#define T_ 512
#define C_ 256
#define F_ 512

static constexpr int F4       = F_ / 4;        // 128 float4 per row
static constexpr int TPB      = 256;
static constexpr int T_CHUNK  = 16;            // rows per K1 CTA
static constexpr int NCHUNK   = T_ / T_CHUNK;  // 32 partial chunks per b
static constexpr int C_CHUNK  = 64;            // rows per K2 CTA
static constexpr int NCC      = C_ / C_CHUNK;  // 4 K2 CTAs per b -> grid 128
static constexpr int REP_ROWS = 16;            // replicated rows in smem (32KB)
static constexpr int BULK_BYTES = REP_ROWS * F_ * 4;          // 32768
static constexpr int NBULK      = C_CHUNK / REP_ROWS;         // 4 copies/CTA

// Partial sums: [B][NCHUNK][F4] float4 (2MB scratch)
__device__ float4 g_part[B_ * NCHUNK * F4];

__device__ __forceinline__ void f4add(float4& a, const float4& b) {
    a.x += b.x; a.y += b.y; a.z += b.z; a.w += b.w;
}

__device__ __forceinline__ uint32_t smem_u32(const void* p) {
    uint32_t a;
    asm("{ .reg .u64 t; cvta.to.shared.u64 t, %1; cvt.u32.u64 %0, t; }"
        : "=r"(a) : "l"(p));
    return a;
}

// ---------------- K1: streaming T-reduction (unchanged; ~8TB/s) -----------
__global__ __launch_bounds__(TPB)
void k1_reduce(const float* __restrict__ x) {
    const int b     = blockIdx.x >> 5;        // /NCHUNK
    const int chunk = blockIdx.x & 31;
    const int f4l   = threadIdx.x & (F4 - 1);
    const int rh    = threadIdx.x >> 7;        // 0 or 1

    const float4* xb = reinterpret_cast<const float4*>(x)
                     + ((size_t)b * T_ + chunk * T_CHUNK + rh) * F4 + f4l;

    float4 v0 = __ldg(&xb[ 0 * F4]);
    float4 v1 = __ldg(&xb[ 2 * F4]);
    float4 v2 = __ldg(&xb[ 4 * F4]);
    float4 v3 = __ldg(&xb[ 6 * F4]);
    float4 v4 = __ldg(&xb[ 8 * F4]);
    float4 v5 = __ldg(&xb[10 * F4]);
    float4 v6 = __ldg(&xb[12 * F4]);
    float4 v7 = __ldg(&xb[14 * F4]);
    f4add(v0, v4); f4add(v1, v5); f4add(v2, v6); f4add(v3, v7);
    f4add(v0, v2); f4add(v1, v3);
    f4add(v0, v1);

    __shared__ float4 sm[TPB];
    sm[threadIdx.x] = v0;
    __syncthreads();
    if (threadIdx.x < F4) {
        float4 tot = sm[threadIdx.x];
        f4add(tot, sm[threadIdx.x + F4]);
        g_part[((size_t)b * NCHUNK + chunk) * F4 + threadIdx.x] = tot;
    }
}

// ---------------- K2: sum partials, broadcast via bulk async stores -------
// CTA (b, cc) owns out[b, cc*64 .. cc*64+64, :] = 128KB, written as 4 bulk
// copies of a 32KB smem buffer holding 16 replicas of the final 2KB row.
__global__ __launch_bounds__(TPB)
void k2_bulkstore(float* __restrict__ out) {
    const int b   = blockIdx.x >> 2;          // /NCC
    const int cc  = blockIdx.x & (NCC - 1);
    const int f4l = threadIdx.x & (F4 - 1);
    const int h   = threadIdx.x >> 7;         // 0/1: each half sums 16 chunks

    __shared__ __align__(128) float4 buf[REP_ROWS * F4];   // 32KB

    // Sum the 32 partial chunks for this b (L2-resident, 2 halves x 16).
    const float4* pb = &g_part[((size_t)b * NCHUNK + h * (NCHUNK / 2)) * F4 + f4l];
    float4 s = make_float4(0.f, 0.f, 0.f, 0.f);
#pragma unroll
    for (int k = 0; k < NCHUNK / 2; ++k)
        f4add(s, pb[(size_t)k * F4]);

    buf[h * F4 + f4l] = s;                    // rows 0,1 as temporaries
    __syncthreads();
    if (threadIdx.x < F4) {
        float4 tot = buf[threadIdx.x];
        f4add(tot, buf[F4 + threadIdx.x]);
        buf[threadIdx.x] = tot;               // row 0 = final column sums
    }
    __syncthreads();

    // Replicate row 0 into rows 1..15 (h=0 -> odd rows, h=1 -> even rows).
    const float4 val = buf[f4l];
#pragma unroll
    for (int r = 1 + h; r < REP_ROWS; r += 2)
        buf[r * F4 + f4l] = val;

    // Make generic-proxy smem writes visible to the async (bulk-copy) proxy.
    asm volatile("fence.proxy.async.shared::cta;" ::: "memory");
    __syncthreads();

    if (threadIdx.x == 0) {
        const uint32_t src = smem_u32(buf);
        char* dst = reinterpret_cast<char*>(
            out + ((size_t)b * C_ + (size_t)cc * C_CHUNK) * F_);
#pragma unroll
        for (int i = 0; i < NBULK; ++i) {
            asm volatile(
                "cp.async.bulk.global.shared::cta.bulk_group [%0], [%1], %2;"
                :: "l"(dst + (size_t)i * BULK_BYTES), "r"(src), "n"(BULK_BYTES)
                : "memory");
        }
        asm volatile("cp.async.bulk.commit_group;" ::: "memory");
        asm volatile("cp.async.bulk.wait_group 0;" ::: "memory");
    }
}

extern "C" void kernel_launch(void* const* d_in, const int* in_sizes, int n_in,
                              void* d_out, int out_size) {
    (void)in_sizes; (void)n_in; (void)out_size;
    const float* x = (const float*)d_in[0];   // [B,T,F]; context/W/b dead
    float* out = (float*)d_out;               // [B,C,F]
    k1_reduce<<<B_ * NCHUNK, TPB>>>(x);
    k2_bulkstore<<<B_ * NCC, TPB>>>(out);
}